// round 2
// baseline (speedup 1.0000x reference)
#include <cuda_runtime.h>
#include <math.h>

// ---------------- problem constants ----------------
#define B 32
#define C 256
#define G 4
#define CG 64          // channels per group
#define H 56
#define W 56
#define HW (H*W)       // 3136
#define OH 28
#define OW 28
#define OHW (OH*OW)    // 784
#define NELEM (B*C*OHW)   // 6,422,528
#define M_PER_C (B*OHW)   // 25088 elements per channel for BN stats
#define BN_EPS 1e-5f

// ---------------- scratch (static device globals; no runtime alloc) ----------------
__device__ unsigned long long g_xbits[B*G*HW];      // packed sign(x): (n,g,h,w), bit i = channel g*64+i is negative
__device__ unsigned long long g_obits[B*G*OHW];     // packed sign(out1): (n,q,oh,ow)
__device__ unsigned long long g_w1bits[C*9];        // per out-channel, per tap
__device__ unsigned long long g_w2bits[C*4];        // per out-channel, 4 words of 64 input channels
__device__ short  g_y1[NELEM];                      // conv1 integer output (|.| <= 576)
__device__ short  g_y2[NELEM];                      // conv2 integer output (|.| <= 256)
__device__ float  g_pool[NELEM];                    // maxpool(x)
__device__ float  g_out1[NELEM];                    // residual x1
__device__ unsigned long long g_sum1[C], g_sq1[C];  // exact int64 BN stats (two's complement)
__device__ unsigned long long g_sum2[C], g_sq2[C];
__device__ float  g_a1[C], g_b1[C], g_a2[C], g_b2[C];

// ---------------- kernels ----------------

// Pack weight signs + zero the stat accumulators for this launch.
__global__ void k_packw(const float* __restrict__ w1, const float* __restrict__ w2) {
    int t = blockIdx.x * blockDim.x + threadIdx.x;
    if (t < C) { g_sum1[t] = 0ull; g_sq1[t] = 0ull; g_sum2[t] = 0ull; g_sq2[t] = 0ull; }
    if (t < C*9) {
        int c = t / 9, tap = t % 9;
        const float* base = w1 + (size_t)(c*CG)*9 + tap;
        unsigned long long b = 0;
        #pragma unroll 8
        for (int i = 0; i < CG; i++)
            b |= (unsigned long long)(base[i*9] < 0.0f) << i;
        g_w1bits[t] = b;
    } else if (t < C*9 + C*4) {
        int u = t - C*9;
        int c = u / 4, q = u % 4;
        const float* base = w2 + (size_t)c*C + q*64;
        unsigned long long b = 0;
        #pragma unroll 8
        for (int i = 0; i < 64; i++)
            b |= (unsigned long long)(base[i] < 0.0f) << i;
        g_w2bits[u] = b;
    }
}

// Pack sign(x) over the 64 channels of each group: one uint64 per (n,g,h,w).
__global__ void k_packx(const float* __restrict__ x) {
    int t = blockIdx.x * blockDim.x + threadIdx.x;
    if (t >= B*G*HW) return;
    int s = t % HW;            // h*W + w
    int g = (t / HW) % G;
    int n = t / (G*HW);
    const float* base = x + ((size_t)(n*C + g*CG))*HW + s;
    unsigned long long b = 0;
    #pragma unroll 8
    for (int i = 0; i < CG; i++)
        b |= (unsigned long long)(base[(size_t)i*HW] < 0.0f) << i;
    g_xbits[t] = b;
}

// maxpool2d(x, k=3, s=2, p=1) -> (B,C,28,28)
__global__ void k_pool(const float* __restrict__ x) {
    int t = blockIdx.x * blockDim.x + threadIdx.x;
    if (t >= NELEM) return;
    int ow = t % OW;
    int oh = (t / OW) % OH;
    int nc = t / OHW;
    const float* base = x + (size_t)nc * HW;
    float m = -INFINITY;
    #pragma unroll
    for (int kh = 0; kh < 3; kh++) {
        int ih = 2*oh - 1 + kh;
        if ((unsigned)ih < H) {
            #pragma unroll
            for (int kw = 0; kw < 3; kw++) {
                int iw = 2*ow - 1 + kw;
                if ((unsigned)iw < W) m = fmaxf(m, base[ih*W + iw]);
            }
        }
    }
    g_pool[t] = m;
}

// Binary grouped 3x3 conv, stride 2, pad 1. One thread per output element.
// blockIdx.y = n*C + c (one (n,c) per block row so stats reduce cleanly).
__global__ void k_conv1() {
    int nc = blockIdx.y;
    int n = nc / C, c = nc % C;
    int g = c >> 6;
    int s = blockIdx.x * blockDim.x + threadIdx.x;

    __shared__ int sh_sum, sh_sq;
    if (threadIdx.x == 0) { sh_sum = 0; sh_sq = 0; }
    __syncthreads();

    int acc = 0;
    if (s < OHW) {
        int ow = s % OW, oh = s / OW;
        const unsigned long long* wb = g_w1bits + c*9;
        const unsigned long long* xb = g_xbits + (size_t)(n*G + g)*HW;
        #pragma unroll
        for (int kh = 0; kh < 3; kh++) {
            int ih = 2*oh - 1 + kh;
            if ((unsigned)ih < H) {
                #pragma unroll
                for (int kw = 0; kw < 3; kw++) {
                    int iw = 2*ow - 1 + kw;
                    if ((unsigned)iw < W)
                        acc += 64 - 2*__popcll(xb[ih*W + iw] ^ wb[kh*3 + kw]);
                }
            }
        }
        g_y1[(size_t)nc*OHW + s] = (short)acc;
    }
    // warp reduce then shared atomics then one global atomic per block
    int wsum = acc, wsq = acc*acc;
    #pragma unroll
    for (int o = 16; o; o >>= 1) {
        wsum += __shfl_down_sync(0xffffffffu, wsum, o);
        wsq  += __shfl_down_sync(0xffffffffu, wsq, o);
    }
    if ((threadIdx.x & 31) == 0) { atomicAdd(&sh_sum, wsum); atomicAdd(&sh_sq, wsq); }
    __syncthreads();
    if (threadIdx.x == 0) {
        atomicAdd(&g_sum1[c], (unsigned long long)(long long)sh_sum);
        atomicAdd(&g_sq1[c],  (unsigned long long)(long long)sh_sq);
    }
}

// BN coefficients from exact integer stats. which=0 -> set 1, which=1 -> set 2.
__global__ void k_coeff(const float* __restrict__ gamma, const float* __restrict__ beta, int which) {
    int c = threadIdx.x;
    long long S = (long long)(which ? g_sum2[c] : g_sum1[c]);
    long long Q = (long long)(which ? g_sq2[c]  : g_sq1[c]);
    double mean = (double)S / (double)M_PER_C;
    double var  = (double)Q / (double)M_PER_C - mean*mean;
    float a = gamma[c] * rsqrtf((float)var + BN_EPS);
    float b = beta[c] - (float)mean * a;
    if (which) { g_a2[c] = a; g_b2[c] = b; }
    else       { g_a1[c] = a; g_b1[c] = b; }
}

// out1 = a1[c]*y1 + b1[c] + pool
__global__ void k_bn1() {
    int t = blockIdx.x * blockDim.x + threadIdx.x;
    if (t >= NELEM) return;
    int c = (t / OHW) % C;
    g_out1[t] = g_a1[c] * (float)g_y1[t] + g_b1[c] + g_pool[t];
}

// Pack sign(out1) over channels: one uint64 per (n,q,oh,ow), q = channel-word 0..3
__global__ void k_packo() {
    int t = blockIdx.x * blockDim.x + threadIdx.x;
    if (t >= B*G*OHW) return;
    int s = t % OHW;
    int q = (t / OHW) % G;
    int n = t / (G*OHW);
    const float* base = g_out1 + ((size_t)(n*C + q*64))*OHW + s;
    unsigned long long b = 0;
    #pragma unroll 8
    for (int i = 0; i < 64; i++)
        b |= (unsigned long long)(base[(size_t)i*OHW] < 0.0f) << i;
    g_obits[t] = b;
}

// Binary 1x1 conv over 256 channels: 4 xor+popcll per output element.
__global__ void k_conv2() {
    int nc = blockIdx.y;
    int n = nc / C, c = nc % C;
    int s = blockIdx.x * blockDim.x + threadIdx.x;

    __shared__ int sh_sum, sh_sq;
    if (threadIdx.x == 0) { sh_sum = 0; sh_sq = 0; }
    __syncthreads();

    int acc = 0;
    if (s < OHW) {
        const unsigned long long* wb = g_w2bits + c*4;
        const unsigned long long* ob = g_obits + (size_t)n*G*OHW + s;
        int pc = 0;
        #pragma unroll
        for (int q = 0; q < 4; q++)
            pc += __popcll(ob[(size_t)q*OHW] ^ wb[q]);
        acc = 256 - 2*pc;
        g_y2[(size_t)nc*OHW + s] = (short)acc;
    }
    int wsum = acc, wsq = acc*acc;
    #pragma unroll
    for (int o = 16; o; o >>= 1) {
        wsum += __shfl_down_sync(0xffffffffu, wsum, o);
        wsq  += __shfl_down_sync(0xffffffffu, wsq, o);
    }
    if ((threadIdx.x & 31) == 0) { atomicAdd(&sh_sum, wsum); atomicAdd(&sh_sq, wsq); }
    __syncthreads();
    if (threadIdx.x == 0) {
        atomicAdd(&g_sum2[c], (unsigned long long)(long long)sh_sum);
        atomicAdd(&g_sq2[c],  (unsigned long long)(long long)sh_sq);
    }
}

// out = a2[c]*y2 + b2[c] + out1
__global__ void k_final(float* __restrict__ out) {
    int t = blockIdx.x * blockDim.x + threadIdx.x;
    if (t >= NELEM) return;
    int c = (t / OHW) % C;
    out[t] = g_a2[c] * (float)g_y2[t] + g_b2[c] + g_out1[t];
}

// ---------------- launch ----------------
extern "C" void kernel_launch(void* const* d_in, const int* in_sizes, int n_in,
                              void* d_out, int out_size) {
    const float* x      = (const float*)d_in[0];
    const float* w1     = (const float*)d_in[1];
    const float* w2     = (const float*)d_in[2];
    const float* gamma1 = (const float*)d_in[3];
    const float* beta1  = (const float*)d_in[4];
    const float* gamma2 = (const float*)d_in[5];
    const float* beta2  = (const float*)d_in[6];
    float* out = (float*)d_out;

    const int T = 256;
    k_packw<<<(C*9 + C*4 + T - 1)/T, T>>>(w1, w2);
    k_packx<<<(B*G*HW + T - 1)/T, T>>>(x);
    k_pool <<<(NELEM + T - 1)/T, T>>>(x);

    dim3 gconv((OHW + T - 1)/T, B*C);
    k_conv1<<<gconv, T>>>();
    k_coeff<<<1, C>>>(gamma1, beta1, 0);
    k_bn1  <<<(NELEM + T - 1)/T, T>>>();
    k_packo<<<(B*G*OHW + T - 1)/T, T>>>();
    k_conv2<<<gconv, T>>>();
    k_coeff<<<1, C>>>(gamma2, beta2, 1);
    k_final<<<(NELEM + T - 1)/T, T>>>(out);
}

// round 3
// speedup vs baseline: 1.1896x; 1.1896x over previous
#include <cuda_runtime.h>
#include <math.h>

typedef unsigned long long ull;

// ---------------- problem constants ----------------
#define B 32
#define C 256
#define G 4
#define CG 64
#define H 56
#define W 56
#define HW (H*W)          // 3136
#define OH 28
#define OW 28
#define OHW (OH*OW)       // 784
#define NELEM (B*C*OHW)   // 6,422,528
#define M_PER_C (B*OHW)   // 25088
#define BN_EPS 1e-5f

// ---------------- scratch ----------------
__device__ ull   g_xbits[B*G*HW];     // packed sign(x): (n,g,h,w)
__device__ ull   g_obits[B*G*OHW];    // packed sign(out1): (n,q,s)
__device__ ull   g_w1bits[C*9];
__device__ ull   g_w2bits[C*4];
__device__ short g_y1[NELEM];
__device__ short g_y2[NELEM];
__device__ float g_pool[NELEM];
__device__ ull   g_sum1[C], g_sq1[C], g_sum2[C], g_sq2[C];
__device__ float g_a1[C], g_b1[C], g_a2[C], g_b2[C];

// ---------------- pack weights + zero stats ----------------
__global__ void k_packw(const float* __restrict__ w1, const float* __restrict__ w2) {
    int t = blockIdx.x * blockDim.x + threadIdx.x;
    if (t < C) { g_sum1[t] = 0ull; g_sq1[t] = 0ull; g_sum2[t] = 0ull; g_sq2[t] = 0ull; }
    if (t < C*9) {
        int c = t / 9, tap = t % 9;
        const float* base = w1 + (size_t)(c*CG)*9 + tap;
        ull b = 0;
        #pragma unroll 8
        for (int i = 0; i < CG; i++)
            b |= (ull)(base[i*9] < 0.0f) << i;
        g_w1bits[t] = b;
    } else if (t < C*9 + C*4) {
        int u = t - C*9;
        int c = u / 4, q = u % 4;
        const float* base = w2 + (size_t)c*C + q*64;
        ull b = 0;
        #pragma unroll 8
        for (int i = 0; i < 64; i++)
            b |= (ull)(base[i] < 0.0f) << i;
        g_w2bits[u] = b;
    }
}

// ---------------- pack sign(x) ----------------
__global__ void k_packx(const float* __restrict__ x) {
    int t = blockIdx.x * blockDim.x + threadIdx.x;
    if (t >= B*G*HW) return;
    int s = t % HW;
    int g = (t / HW) % G;
    int n = t / (G*HW);
    const float* base = x + ((size_t)(n*C + g*CG))*HW + s;
    ull b = 0;
    #pragma unroll 8
    for (int i = 0; i < CG; i++)
        b |= (ull)(base[(size_t)i*HW] < 0.0f) << i;
    g_xbits[t] = b;
}

// ---------------- maxpool 3x3 s2 p1 ----------------
__global__ void k_pool(const float* __restrict__ x) {
    int t = blockIdx.x * blockDim.x + threadIdx.x;
    if (t >= NELEM) return;
    int ow = t % OW;
    int oh = (t / OW) % OH;
    int nc = t / OHW;
    const float* base = x + (size_t)nc * HW;
    float m = -INFINITY;
    #pragma unroll
    for (int kh = 0; kh < 3; kh++) {
        int ih = 2*oh - 1 + kh;
        if ((unsigned)ih < H) {
            #pragma unroll
            for (int kw = 0; kw < 3; kw++) {
                int iw = 2*ow - 1 + kw;
                if ((unsigned)iw < W) m = fmaxf(m, base[ih*W + iw]);
            }
        }
    }
    g_pool[t] = m;
}

// ---------------- conv1: binary grouped 3x3, s2, p1 ----------------
// grid (chunk=4, g=4, n=32); block 256 = 16 channel-slots x 16 spatial-slots.
// smem tile: 15 rows x 58 cols of xbits (zero-padded), weights for 4 channels
// per thread in registers. Pads only occur at oh==0 / ow==0; corrected in a
// rarely-taken branch.
__global__ void __launch_bounds__(256, 2) k_conv1() {
    __shared__ ull tile[15*58];
    int chunk = blockIdx.x;       // 0..3, oh0 = chunk*7
    int g = blockIdx.y;
    int n = blockIdx.z;
    int tid = threadIdx.x;
    int oh0 = chunk * 7;
    int ih0 = 2*oh0 - 1;

    // load tile (zero padded)
    const ull* xb = g_xbits + (size_t)(n*G + g)*HW;
    for (int idx = tid; idx < 15*58; idx += 256) {
        int r = idx / 58, tc = idx % 58;
        ull v = 0;
        int ih = ih0 + r;
        if (tc >= 1 && tc <= 56 && (unsigned)ih < H)
            v = xb[ih*W + (tc-1)];
        tile[idx] = v;
    }

    int cs = tid >> 4;            // 0..15 channel slot (4 channels each)
    int ss = tid & 15;            // 0..15 spatial slot
    int c0 = g*64 + cs*4;         // first of 4 channels

    ull wr[4][9];
    #pragma unroll
    for (int j = 0; j < 4; j++)
        #pragma unroll
        for (int t = 0; t < 9; t++)
            wr[j][t] = g_w1bits[(c0+j)*9 + t];

    __syncthreads();

    int ssum[4] = {0,0,0,0}, ssq[4] = {0,0,0,0};
    size_t outbase = (size_t)(n*C + c0)*OHW + oh0*OW;

    for (int p = ss; p < 7*OW; p += 16) {
        int oh_l = p / OW;
        int ow = p - oh_l*OW;
        const ull* tr = &tile[(2*oh_l)*58 + 2*ow];
        ull x0 = tr[0],      x1 = tr[1],      x2 = tr[2];
        ull x3 = tr[58],     x4 = tr[59],     x5 = tr[60];
        ull x6 = tr[116],    x7 = tr[117],    x8 = tr[118];

        bool bh = (oh0 == 0 && oh_l == 0);
        bool bw = (ow == 0);

        int acc[4];
        #pragma unroll
        for (int j = 0; j < 4; j++) {
            int pc = __popcll(x0 ^ wr[j][0]) + __popcll(x1 ^ wr[j][1]) + __popcll(x2 ^ wr[j][2])
                   + __popcll(x3 ^ wr[j][3]) + __popcll(x4 ^ wr[j][4]) + __popcll(x5 ^ wr[j][5])
                   + __popcll(x6 ^ wr[j][6]) + __popcll(x7 ^ wr[j][7]) + __popcll(x8 ^ wr[j][8]);
            acc[j] = 576 - 2*pc;
        }
        if (bh | bw) {
            #pragma unroll
            for (int j = 0; j < 4; j++) {
                if (bh) acc[j] -= 192 - 2*(__popcll(wr[j][0]) + __popcll(wr[j][1]) + __popcll(wr[j][2]));
                if (bw) acc[j] -= 192 - 2*(__popcll(wr[j][0]) + __popcll(wr[j][3]) + __popcll(wr[j][6]));
                if (bh && bw) acc[j] += 64 - 2*__popcll(wr[j][0]);
            }
        }
        #pragma unroll
        for (int j = 0; j < 4; j++) {
            g_y1[outbase + (size_t)j*OHW + p] = (short)acc[j];
            ssum[j] += acc[j];
            ssq[j]  += acc[j]*acc[j];
        }
    }

    // reduce over the 16 spatial slots (16-lane segments of each warp)
    #pragma unroll
    for (int j = 0; j < 4; j++) {
        int s = ssum[j], q = ssq[j];
        #pragma unroll
        for (int o = 8; o; o >>= 1) {
            s += __shfl_down_sync(0xffffffffu, s, o, 16);
            q += __shfl_down_sync(0xffffffffu, q, o, 16);
        }
        if (ss == 0) {
            atomicAdd(&g_sum1[c0+j], (ull)(long long)s);
            atomicAdd(&g_sq1[c0+j],  (ull)(long long)q);
        }
    }
}

// ---------------- BN coefficients ----------------
__global__ void k_coeff(const float* __restrict__ gamma, const float* __restrict__ beta, int which) {
    int c = threadIdx.x;
    long long S = (long long)(which ? g_sum2[c] : g_sum1[c]);
    long long Q = (long long)(which ? g_sq2[c]  : g_sq1[c]);
    double mean = (double)S / (double)M_PER_C;
    double var  = (double)Q / (double)M_PER_C - mean*mean;
    float a = gamma[c] * rsqrtf((float)var + BN_EPS);
    float b = beta[c] - (float)mean * a;
    if (which) { g_a2[c] = a; g_b2[c] = b; }
    else       { g_a1[c] = a; g_b1[c] = b; }
}

// ---------------- fused bn1 + sign-pack (no out1 array) ----------------
// grid (sc=2, q=4, n=32); block 256 = 8 warps, each warp handles 8 channel rows.
__global__ void k_bnpack() {
    __shared__ unsigned char sb[64*396];
    int sc = blockIdx.x;          // 0..1, 392 spatial each
    int q  = blockIdx.y;          // channel word 0..3
    int n  = blockIdx.z;
    int tid  = threadIdx.x;
    int w    = tid >> 5;
    int lane = tid & 31;
    int sbase = sc * 392;

    #pragma unroll
    for (int r = 0; r < 8; r++) {
        int cl = w*8 + r;                 // 0..63
        int c  = q*64 + cl;
        float a = g_a1[c], b = g_b1[c];
        size_t base = (size_t)(n*C + c)*OHW + sbase;
        for (int s = lane; s < 392; s += 32) {
            float v = a * (float)g_y1[base + s] + b + g_pool[base + s];
            sb[cl*396 + s] = (v < 0.0f);
        }
    }
    __syncthreads();

    for (int s = tid; s < 392; s += 256) {
        ull bword = 0;
        #pragma unroll 16
        for (int cl = 0; cl < 64; cl++)
            bword |= (ull)sb[cl*396 + s] << cl;
        g_obits[(size_t)(n*G + q)*OHW + sbase + s] = bword;
    }
}

// ---------------- conv2: binary 1x1, 256 ch ----------------
// grid (sc=7, cgset=4, n=32); block 256 = 8 warps; warp = one channel group of
// 8 channels, lanes = 32 contiguous spatial. Weights (8x4 u64) in registers.
__global__ void __launch_bounds__(256, 2) k_conv2() {
    __shared__ ull ot[4*112];
    int sc = blockIdx.x;          // 0..6, 112 spatial each
    int cgset = blockIdx.y;       // 0..3
    int n  = blockIdx.z;
    int tid  = threadIdx.x;
    int w    = tid >> 5;
    int lane = tid & 31;
    int sbase = sc * 112;

    for (int idx = tid; idx < 4*112; idx += 256) {
        int qq = idx / 112, s = idx % 112;
        ot[idx] = g_obits[(size_t)(n*G + qq)*OHW + sbase + s];
    }

    int c0 = (cgset*8 + w) * 8;   // first of 8 channels for this warp
    ull wr[8][4];
    #pragma unroll
    for (int j = 0; j < 8; j++)
        #pragma unroll
        for (int qq = 0; qq < 4; qq++)
            wr[j][qq] = g_w2bits[(c0+j)*4 + qq];

    __syncthreads();

    int ssum[8] = {0,0,0,0,0,0,0,0}, ssq[8] = {0,0,0,0,0,0,0,0};
    size_t outbase = (size_t)(n*C + c0)*OHW + sbase;

    for (int s = lane; s < 112; s += 32) {
        ull x0 = ot[0*112 + s], x1 = ot[1*112 + s], x2 = ot[2*112 + s], x3 = ot[3*112 + s];
        #pragma unroll
        for (int j = 0; j < 8; j++) {
            int pc = __popcll(x0 ^ wr[j][0]) + __popcll(x1 ^ wr[j][1])
                   + __popcll(x2 ^ wr[j][2]) + __popcll(x3 ^ wr[j][3]);
            int acc = 256 - 2*pc;
            g_y2[outbase + (size_t)j*OHW + s] = (short)acc;
            ssum[j] += acc;
            ssq[j]  += acc*acc;
        }
    }

    #pragma unroll
    for (int j = 0; j < 8; j++) {
        int s = ssum[j], qv = ssq[j];
        #pragma unroll
        for (int o = 16; o; o >>= 1) {
            s  += __shfl_down_sync(0xffffffffu, s,  o);
            qv += __shfl_down_sync(0xffffffffu, qv, o);
        }
        if (lane == 0) {
            atomicAdd(&g_sum2[c0+j], (ull)(long long)s);
            atomicAdd(&g_sq2[c0+j],  (ull)(long long)qv);
        }
    }
}

// ---------------- final: out = bn2(y2) + bn1(y1) + pool ----------------
__global__ void k_final(float* __restrict__ out) {
    int t = blockIdx.x * blockDim.x + threadIdx.x;
    if (t >= NELEM) return;
    int c = (t / OHW) % C;
    float v1 = fmaf(g_a1[c], (float)g_y1[t], g_b1[c]) + g_pool[t];
    out[t] = fmaf(g_a2[c], (float)g_y2[t], g_b2[c]) + v1;
}

// ---------------- launch ----------------
extern "C" void kernel_launch(void* const* d_in, const int* in_sizes, int n_in,
                              void* d_out, int out_size) {
    const float* x      = (const float*)d_in[0];
    const float* w1     = (const float*)d_in[1];
    const float* w2     = (const float*)d_in[2];
    const float* gamma1 = (const float*)d_in[3];
    const float* beta1  = (const float*)d_in[4];
    const float* gamma2 = (const float*)d_in[5];
    const float* beta2  = (const float*)d_in[6];
    float* out = (float*)d_out;

    const int T = 256;
    k_packw<<<(C*9 + C*4 + T - 1)/T, T>>>(w1, w2);
    k_packx<<<(B*G*HW + T - 1)/T, T>>>(x);
    k_pool <<<(NELEM + T - 1)/T, T>>>(x);

    k_conv1<<<dim3(4, G, B), T>>>();
    k_coeff<<<1, C>>>(gamma1, beta1, 0);
    k_bnpack<<<dim3(2, G, B), T>>>();
    k_conv2<<<dim3(7, 4, B), T>>>();
    k_coeff<<<1, C>>>(gamma2, beta2, 1);
    k_final<<<(NELEM + T - 1)/T, T>>>(out);
}

// round 4
// speedup vs baseline: 1.3537x; 1.1380x over previous
#include <cuda_runtime.h>
#include <math.h>

typedef unsigned long long ull;

// ---------------- problem constants ----------------
#define B 32
#define C 256
#define G 4
#define CG 64
#define H 56
#define W 56
#define HW (H*W)          // 3136
#define OH 28
#define OW 28
#define OHW (OH*OW)       // 784
#define NELEM (B*C*OHW)   // 6,422,528
#define M_PER_C (B*OHW)   // 25088
#define BN_EPS 1e-5f

// ---------------- scratch ----------------
__device__ ull   g_xbits[B*G*HW];     // packed sign(x): (n,g,h,w)
__device__ ull   g_obits[B*G*OHW];    // packed sign(out1): (n,q,s)
__device__ ull   g_w1bits[C*9];
__device__ ull   g_w2bits[C*4];
__device__ short g_y1[NELEM];
__device__ short g_y2[NELEM];
__device__ float g_pool[NELEM];
__device__ ull   g_sum1[C], g_sq1[C], g_sum2[C], g_sq2[C];
__device__ float g_a1[C], g_b1[C], g_a2[C], g_b2[C];

// ---------------- pack weights + zero stats ----------------
__global__ void k_packw(const float* __restrict__ w1, const float* __restrict__ w2) {
    int t = blockIdx.x * blockDim.x + threadIdx.x;
    if (t < C) { g_sum1[t] = 0ull; g_sq1[t] = 0ull; g_sum2[t] = 0ull; g_sq2[t] = 0ull; }
    if (t < C*9) {
        int c = t / 9, tap = t % 9;
        const float* base = w1 + (size_t)(c*CG)*9 + tap;
        ull b = 0;
        #pragma unroll 8
        for (int i = 0; i < CG; i++)
            b |= (ull)(base[i*9] < 0.0f) << i;
        g_w1bits[t] = b;
    } else if (t < C*9 + C*4) {
        int u = t - C*9;
        int c = u / 4, q = u % 4;
        const float* base = w2 + (size_t)c*C + q*64;
        ull b = 0;
        #pragma unroll 8
        for (int i = 0; i < 64; i++)
            b |= (ull)(base[i] < 0.0f) << i;
        g_w2bits[u] = b;
    }
}

// ---------------- pack sign(x): 2 words per thread via float2 ----------------
__global__ void k_packx(const float* __restrict__ x) {
    int t = blockIdx.x * blockDim.x + threadIdx.x;
    if (t >= B*G*HW/2) return;
    int s0 = (t % (HW/2)) * 2;
    int g = (t / (HW/2)) % G;
    int n = t / (G*HW/2);
    const float* base = x + ((size_t)(n*C + g*CG))*HW + s0;
    ull b0 = 0, b1 = 0;
    #pragma unroll 8
    for (int i = 0; i < CG; i++) {
        float2 v = *(const float2*)(base + (size_t)i*HW);
        b0 |= (ull)(v.x < 0.0f) << i;
        b1 |= (ull)(v.y < 0.0f) << i;
    }
    ull* dst = g_xbits + (size_t)(n*G + g)*HW + s0;
    dst[0] = b0;
    dst[1] = b1;
}

// ---------------- maxpool 3x3 s2 p1 ----------------
__global__ void k_pool(const float* __restrict__ x) {
    int t = blockIdx.x * blockDim.x + threadIdx.x;
    if (t >= NELEM) return;
    int ow = t % OW;
    int oh = (t / OW) % OH;
    int nc = t / OHW;
    const float* base = x + (size_t)nc * HW;
    float m = -INFINITY;
    #pragma unroll
    for (int kh = 0; kh < 3; kh++) {
        int ih = 2*oh - 1 + kh;
        if ((unsigned)ih < H) {
            #pragma unroll
            for (int kw = 0; kw < 3; kw++) {
                int iw = 2*ow - 1 + kw;
                if ((unsigned)iw < W) m = fmaxf(m, base[ih*W + iw]);
            }
        }
    }
    g_pool[t] = m;
}

// ---------------- conv1: binary grouped 3x3, s2, p1 ----------------
// grid (chunk=7, g=4, n=32): 4 output rows per block. block 256 =
// 32 channel-slots (2 channels each) x 8 spatial-slots. smem tile 9x58
// zero-padded; weights in registers (18 u64). Pads only at oh==0 / ow==0.
__global__ void __launch_bounds__(256, 3) k_conv1() {
    __shared__ ull tile[9*58];
    int chunk = blockIdx.x;       // 0..6, oh0 = chunk*4
    int g = blockIdx.y;
    int n = blockIdx.z;
    int tid = threadIdx.x;
    int oh0 = chunk * 4;
    int ih0 = 2*oh0 - 1;

    const ull* xb = g_xbits + (size_t)(n*G + g)*HW;
    for (int idx = tid; idx < 9*58; idx += 256) {
        int r = idx / 58, tc = idx % 58;
        ull v = 0;
        int ih = ih0 + r;
        if (tc >= 1 && tc <= 56 && (unsigned)ih < H)
            v = xb[ih*W + (tc-1)];
        tile[idx] = v;
    }

    int cs = tid >> 3;            // 0..31 channel slot (2 channels each)
    int ss = tid & 7;             // 0..7 spatial slot
    int c0 = g*64 + cs*2;

    ull wr[2][9];
    #pragma unroll
    for (int j = 0; j < 2; j++)
        #pragma unroll
        for (int t = 0; t < 9; t++)
            wr[j][t] = g_w1bits[(c0+j)*9 + t];

    __syncthreads();

    int ssum[2] = {0,0}, ssq[2] = {0,0};
    size_t outbase = (size_t)(n*C + c0)*OHW + oh0*OW;

    for (int p = ss; p < 4*OW; p += 8) {
        int oh_l = p / OW;
        int ow = p - oh_l*OW;
        const ull* tr = &tile[(2*oh_l)*58 + 2*ow];
        ull x0 = tr[0],    x1 = tr[1],    x2 = tr[2];
        ull x3 = tr[58],   x4 = tr[59],   x5 = tr[60];
        ull x6 = tr[116],  x7 = tr[117],  x8 = tr[118];

        bool bh = (chunk == 0 && oh_l == 0);
        bool bw = (ow == 0);

        int acc[2];
        #pragma unroll
        for (int j = 0; j < 2; j++) {
            int pc = __popcll(x0 ^ wr[j][0]) + __popcll(x1 ^ wr[j][1]) + __popcll(x2 ^ wr[j][2])
                   + __popcll(x3 ^ wr[j][3]) + __popcll(x4 ^ wr[j][4]) + __popcll(x5 ^ wr[j][5])
                   + __popcll(x6 ^ wr[j][6]) + __popcll(x7 ^ wr[j][7]) + __popcll(x8 ^ wr[j][8]);
            acc[j] = 576 - 2*pc;
        }
        if (bh | bw) {
            #pragma unroll
            for (int j = 0; j < 2; j++) {
                if (bh) acc[j] -= 192 - 2*(__popcll(wr[j][0]) + __popcll(wr[j][1]) + __popcll(wr[j][2]));
                if (bw) acc[j] -= 192 - 2*(__popcll(wr[j][0]) + __popcll(wr[j][3]) + __popcll(wr[j][6]));
                if (bh && bw) acc[j] += 64 - 2*__popcll(wr[j][0]);
            }
        }
        #pragma unroll
        for (int j = 0; j < 2; j++) {
            g_y1[outbase + (size_t)j*OHW + p] = (short)acc[j];
            ssum[j] += acc[j];
            ssq[j]  += acc[j]*acc[j];
        }
    }

    // reduce across the 8 spatial slots (8-lane segments)
    #pragma unroll
    for (int j = 0; j < 2; j++) {
        int s = ssum[j], q = ssq[j];
        #pragma unroll
        for (int o = 4; o; o >>= 1) {
            s += __shfl_down_sync(0xffffffffu, s, o, 8);
            q += __shfl_down_sync(0xffffffffu, q, o, 8);
        }
        if (ss == 0) {
            atomicAdd(&g_sum1[c0+j], (ull)(long long)s);
            atomicAdd(&g_sq1[c0+j],  (ull)(long long)q);
        }
    }
}

// ---------------- BN coefficients ----------------
__global__ void k_coeff(const float* __restrict__ gamma, const float* __restrict__ beta, int which) {
    int c = threadIdx.x;
    long long S = (long long)(which ? g_sum2[c] : g_sum1[c]);
    long long Q = (long long)(which ? g_sq2[c]  : g_sq1[c]);
    double mean = (double)S / (double)M_PER_C;
    double var  = (double)Q / (double)M_PER_C - mean*mean;
    float a = gamma[c] * rsqrtf((float)var + BN_EPS);
    float b = beta[c] - (float)mean * a;
    if (which) { g_a2[c] = a; g_b2[c] = b; }
    else       { g_a1[c] = a; g_b1[c] = b; }
}

// ---------------- fused bn1 + sign-pack (no out1 array) ----------------
__global__ void k_bnpack() {
    __shared__ unsigned char sb[64*396];
    int sc = blockIdx.x;          // 0..1, 392 spatial each
    int q  = blockIdx.y;          // channel word 0..3
    int n  = blockIdx.z;
    int tid  = threadIdx.x;
    int w    = tid >> 5;
    int lane = tid & 31;
    int sbase = sc * 392;

    #pragma unroll
    for (int r = 0; r < 8; r++) {
        int cl = w*8 + r;
        int c  = q*64 + cl;
        float a = g_a1[c], b = g_b1[c];
        size_t base = (size_t)(n*C + c)*OHW + sbase;
        for (int s = lane; s < 392; s += 32) {
            float v = a * (float)g_y1[base + s] + b + g_pool[base + s];
            sb[cl*396 + s] = (v < 0.0f);
        }
    }
    __syncthreads();

    for (int s = tid; s < 392; s += 256) {
        ull bword = 0;
        #pragma unroll 16
        for (int cl = 0; cl < 64; cl++)
            bword |= (ull)sb[cl*396 + s] << cl;
        g_obits[(size_t)(n*G + q)*OHW + sbase + s] = bword;
    }
}

// ---------------- conv2: binary 1x1, 256 ch ----------------
// grid (sc=7, cgset=8, n=32); block 256 = 8 warps; warp = 4 channels,
// lanes = spatial. Weights (4x4 u64 = 32 regs) in registers.
__global__ void __launch_bounds__(256) k_conv2() {
    __shared__ ull ot[4*112];
    int sc = blockIdx.x;          // 0..6, 112 spatial each
    int cgset = blockIdx.y;       // 0..7
    int n  = blockIdx.z;
    int tid  = threadIdx.x;
    int w    = tid >> 5;
    int lane = tid & 31;
    int sbase = sc * 112;

    for (int idx = tid; idx < 4*112; idx += 256) {
        int qq = idx / 112, s = idx % 112;
        ot[idx] = g_obits[(size_t)(n*G + qq)*OHW + sbase + s];
    }

    int c0 = (cgset*8 + w) * 4;   // 4 channels per warp
    ull wr[4][4];
    #pragma unroll
    for (int j = 0; j < 4; j++)
        #pragma unroll
        for (int qq = 0; qq < 4; qq++)
            wr[j][qq] = g_w2bits[(c0+j)*4 + qq];

    __syncthreads();

    int ssum[4] = {0,0,0,0}, ssq[4] = {0,0,0,0};
    size_t outbase = (size_t)(n*C + c0)*OHW + sbase;

    for (int s = lane; s < 112; s += 32) {
        ull x0 = ot[s], x1 = ot[112 + s], x2 = ot[224 + s], x3 = ot[336 + s];
        #pragma unroll
        for (int j = 0; j < 4; j++) {
            int pc = __popcll(x0 ^ wr[j][0]) + __popcll(x1 ^ wr[j][1])
                   + __popcll(x2 ^ wr[j][2]) + __popcll(x3 ^ wr[j][3]);
            int acc = 256 - 2*pc;
            g_y2[outbase + (size_t)j*OHW + s] = (short)acc;
            ssum[j] += acc;
            ssq[j]  += acc*acc;
        }
    }

    #pragma unroll
    for (int j = 0; j < 4; j++) {
        int s = ssum[j], qv = ssq[j];
        #pragma unroll
        for (int o = 16; o; o >>= 1) {
            s  += __shfl_down_sync(0xffffffffu, s,  o);
            qv += __shfl_down_sync(0xffffffffu, qv, o);
        }
        if (lane == 0) {
            atomicAdd(&g_sum2[c0+j], (ull)(long long)s);
            atomicAdd(&g_sq2[c0+j],  (ull)(long long)qv);
        }
    }
}

// ---------------- final: out = bn2(y2) + bn1(y1) + pool, 4 elems/thread ----------------
__global__ void k_final(float* __restrict__ out) {
    int t = blockIdx.x * blockDim.x + threadIdx.x;    // vector index
    if (t >= NELEM/4) return;
    int c = (t / (OHW/4)) % C;                        // OHW/4 = 196, exact
    float a1 = g_a1[c], b1 = g_b1[c], a2 = g_a2[c], b2 = g_b2[c];
    short4 y1 = ((const short4*)g_y1)[t];
    short4 y2 = ((const short4*)g_y2)[t];
    float4 p  = ((const float4*)g_pool)[t];
    float4 r;
    r.x = fmaf(a2, (float)y2.x, b2) + fmaf(a1, (float)y1.x, b1) + p.x;
    r.y = fmaf(a2, (float)y2.y, b2) + fmaf(a1, (float)y1.y, b1) + p.y;
    r.z = fmaf(a2, (float)y2.z, b2) + fmaf(a1, (float)y1.z, b1) + p.z;
    r.w = fmaf(a2, (float)y2.w, b2) + fmaf(a1, (float)y1.w, b1) + p.w;
    ((float4*)out)[t] = r;
}

// ---------------- launch ----------------
extern "C" void kernel_launch(void* const* d_in, const int* in_sizes, int n_in,
                              void* d_out, int out_size) {
    const float* x      = (const float*)d_in[0];
    const float* w1     = (const float*)d_in[1];
    const float* w2     = (const float*)d_in[2];
    const float* gamma1 = (const float*)d_in[3];
    const float* beta1  = (const float*)d_in[4];
    const float* gamma2 = (const float*)d_in[5];
    const float* beta2  = (const float*)d_in[6];
    float* out = (float*)d_out;

    const int T = 256;
    k_packw<<<(C*9 + C*4 + T - 1)/T, T>>>(w1, w2);
    k_packx<<<(B*G*HW/2 + T - 1)/T, T>>>(x);
    k_pool <<<(NELEM + T - 1)/T, T>>>(x);

    k_conv1<<<dim3(7, G, B), T>>>();
    k_coeff<<<1, C>>>(gamma1, beta1, 0);
    k_bnpack<<<dim3(2, G, B), T>>>();
    k_conv2<<<dim3(7, 8, B), T>>>();
    k_coeff<<<1, C>>>(gamma2, beta2, 1);
    k_final<<<(NELEM/4 + T - 1)/T, T>>>(out);
}